// round 16
// baseline (speedup 1.0000x reference)
#include <cuda_runtime.h>
#include <cuda_bf16.h>
#include <math.h>

#define B       32
#define HID     1024
#define K2      2048
#define V       32000
#define TSTEPS  64
#define NROWS   4096
#define KSPLIT  8
#define KCHUNK  256
#define START_TOK 1

// ================= persistent device scratch =================
__device__ float g_Wt0[(size_t)K2*NROWS];   // layer0 [Wih|Whh]^T [k][row]  (fp32)
__device__ float g_Wt1[(size_t)K2*NROWS];
__device__ uint4 g_WL[(size_t)V*256];       // W_lin 2-split bf16 interleaved
__device__ uint4 g_XL[32*256];              // h1 2-split bf16
__device__ float g_h0[B*HID], g_c0[B*HID], g_h1[B*HID], g_c1[B*HID];
__device__ float g_part[(size_t)KSPLIT*NROWS*B];
__device__ float g_logits[(size_t)B*V];
__device__ int   g_tok[B];
__device__ float g_pm[B*8], g_ps[B*8];
__device__ float g_cv[B*8];
__device__ int   g_ci[B*8];

// ================= f32x2 helpers (accumulation chains FROZEN, R7 bitwise) =================
static __device__ __forceinline__ unsigned long long ffma2(unsigned long long a,
                                                           unsigned long long b,
                                                           unsigned long long c){
    unsigned long long d;
    asm("fma.rn.f32x2 %0, %1, %2, %3;" : "=l"(d) : "l"(a), "l"(b), "l"(c));
    return d;
}
static __device__ __forceinline__ unsigned long long pack2(float x, float y){
    unsigned long long d;
    asm("mov.b64 %0, {%1, %2};" : "=l"(d) : "f"(x), "f"(y));
    return d;
}
static __device__ __forceinline__ float2 unpack2(unsigned long long a){
    float2 r;
    asm("mov.b64 {%0, %1}, %2;" : "=f"(r.x), "=f"(r.y) : "l"(a));
    return r;
}
static __device__ __forceinline__ float sigmoidf_(float x){ return 1.0f/(1.0f + expf(-x)); }

// ================= bf16 helpers (logits path) =================
static __device__ __forceinline__ unsigned short f2bf(float x){
    __nv_bfloat16 h = __float2bfloat16(x);
    return *reinterpret_cast<unsigned short*>(&h);
}
static __device__ __forceinline__ float bf2f(unsigned short u){
    __nv_bfloat16 h = *reinterpret_cast<__nv_bfloat16*>(&u);
    return __bfloat162float(h);
}
static __device__ __forceinline__ uint4 pack4(float4 v){
    unsigned short hx=f2bf(v.x), hy=f2bf(v.y), hz=f2bf(v.z), hw=f2bf(v.w);
    unsigned short lx=f2bf(v.x-bf2f(hx)), ly=f2bf(v.y-bf2f(hy));
    unsigned short lz=f2bf(v.z-bf2f(hz)), lw=f2bf(v.w-bf2f(hw));
    uint4 o;
    o.x = (unsigned)hx | ((unsigned)hy<<16);
    o.y = (unsigned)lx | ((unsigned)ly<<16);
    o.z = (unsigned)hz | ((unsigned)hw<<16);
    o.w = (unsigned)lz | ((unsigned)lw<<16);
    return o;
}
static __device__ __forceinline__ void store_hl(unsigned short* rowbase, int k, float v){
    unsigned short hi = f2bf(v);
    unsigned short lo = f2bf(v - bf2f(hi));
    int idx = (k>>2)*8 + ((k>>1)&1)*4 + (k&1);
    rowbase[idx]   = hi;
    rowbase[idx+2] = lo;
}
static __device__ __forceinline__ void cpa16(void* dst, const void* src){
    unsigned ds = (unsigned)__cvta_generic_to_shared(dst);
    asm volatile("cp.async.cg.shared.global [%0], [%1], 16;\n" :: "r"(ds), "l"(src));
}
#define CP_COMMIT asm volatile("cp.async.commit_group;\n")
#define CP_WAIT(n) asm volatile("cp.async.wait_group %0;\n" :: "n"(n))
static __device__ __forceinline__ uint2 ld2(const char* base, int row, int pair){
    return *(const uint2*)(base + row*544 + pair*8);
}
static __device__ __forceinline__ void mma16816(float* d,
    unsigned a0, unsigned a1, unsigned a2, unsigned a3, unsigned b0, unsigned b1){
    asm volatile("mma.sync.aligned.m16n8k16.row.col.f32.bf16.bf16.f32 "
        "{%0,%1,%2,%3},{%4,%5,%6,%7},{%8,%9},{%0,%1,%2,%3};"
        : "+f"(d[0]), "+f"(d[1]), "+f"(d[2]), "+f"(d[3])
        : "r"(a0), "r"(a1), "r"(a2), "r"(a3), "r"(b0), "r"(b1));
}

// ================= init =================
__global__ void init_kernel(){
    int i = blockIdx.x*blockDim.x + threadIdx.x;
    if (i < B*HID){ g_h0[i]=0.f; g_c0[i]=0.f; g_h1[i]=0.f; g_c1[i]=0.f; }
    if (i < 8192) ((uint4*)g_XL)[i] = make_uint4(0,0,0,0);
    if (i < B) g_tok[i] = START_TOK;
}

// ================= prep =================
template<int L>
__global__ void tr_lstm(const float* __restrict__ Wih, const float* __restrict__ Whh){
    __shared__ float t[32][33];
    int rb = blockIdx.x*32, kb = blockIdx.y*32;
    int x = threadIdx.x, y = threadIdx.y;
    const float* src = (kb < 1024) ? Wih : Whh;
    int ko = (kb < 1024) ? kb : kb - 1024;
    #pragma unroll
    for (int j = 0; j < 32; j += 8) t[y+j][x] = src[(size_t)(rb+y+j)*1024 + ko + x];
    __syncthreads();
    float* dst = L ? g_Wt1 : g_Wt0;
    #pragma unroll
    for (int j = 0; j < 32; j += 8) dst[(size_t)(kb+y+j)*NROWS + rb + x] = t[x][y+j];
}
__global__ void prep_lin(const float* __restrict__ W){
    int v = blockIdx.x, j = threadIdx.x;
    float4 x = *(const float4*)(W + (size_t)v*1024 + j*4);
    g_WL[(size_t)v*256 + j] = pack4(x);
}

// ================= LSTM GEMM partials — 4-deep cp.async W pipeline + pinned LDS software pipeline =====
// 256 blocks x 512 thr. row = tid&127, bq = tid>>7.
// Per-(row,batch) FFMA2 chains bitwise identical to R7 (k ascending, same operands,
// same j order, same outputs). asm-volatile LDS rotation (prefetch distance 3) pins
// the load schedule so ptxas cannot fold it back into per-k latency chains.
template<int L>
__global__ void __launch_bounds__(512) lstm_gemm(const float* __restrict__ emb,
                                                 const float* __restrict__ ctx)
{
    extern __shared__ __align__(16) float smf[];
    float* Xs = smf;                 // [256][32] = 8192 floats (32KB)
    float* Wb = smf + 8192;          // [4][32][128] = 16384 floats (64KB)
    const int tid   = threadIdx.x;
    const int split = blockIdx.x & 7;
    const int row   = (blockIdx.x >> 3)*128 + (tid & 127);
    const int lrow  = tid & 127;
    const int bq    = tid >> 7;           // 0..3
    const int kbase = split*KCHUNK;
    const float* __restrict__ Wt = L ? g_Wt1 : g_Wt0;
    const float* __restrict__ wsrc = Wt + (size_t)kbase*NROWS + (blockIdx.x >> 3)*128;

    // ---- stage X chunk (same contents as R7/R14) ----
    {
        int b = tid >> 4, q = tid & 15;
        const float* src;
        if (L == 0){
            if (split < 2)      src = emb + (size_t)g_tok[b]*512 + kbase;
            else if (split < 4) src = ctx + (size_t)b*512 + (kbase - 512);
            else                src = g_h0 + b*HID + (kbase - 1024);
        } else {
            if (split < 4)      src = g_h0 + b*HID + kbase;
            else                src = g_h1 + b*HID + (kbase - 1024);
        }
        #pragma unroll
        for (int i = 0; i < 4; i++){
            int kf = (q + i*16)*4;
            float4 v = *(const float4*)(src + kf);
            Xs[(kf+0)*32+b]=v.x; Xs[(kf+1)*32+b]=v.y;
            Xs[(kf+2)*32+b]=v.z; Xs[(kf+3)*32+b]=v.w;
        }
    }

    // ---- prefetch W slices 0..2 (3 groups in flight) ----
    #pragma unroll
    for (int p = 0; p < 3; p++){
        float* dst = Wb + p*4096;
        #pragma unroll
        for (int j = 0; j < 2; j++){
            int id = tid + j*512;
            int kk = id >> 5, c = id & 31;
            cpa16(dst + kk*128 + c*4, wsrc + (size_t)(p*32 + kk)*NROWS + c*4);
        }
        CP_COMMIT;
    }

    unsigned long long acc[4] = {0ull,0ull,0ull,0ull};

    const unsigned xsb = (unsigned)__cvta_generic_to_shared(Xs);
    const unsigned wbb = (unsigned)__cvta_generic_to_shared(Wb);

    float wS[4];
    unsigned long long xS[4][4];

#define LDSET(S, KK) do{                                                         \
        unsigned wa_ = woff + (unsigned)(KK)*512u + ((unsigned)lrow << 2);       \
        unsigned xa_ = xoff + (unsigned)(KK)*128u;                               \
        asm volatile("ld.shared.f32 %0, [%1];" : "=f"(wS[S]) : "r"(wa_));        \
        asm volatile("ld.shared.v2.u64 {%0,%1}, [%2];"                           \
                     : "=l"(xS[S][0]), "=l"(xS[S][1]) : "r"(xa_));               \
        asm volatile("ld.shared.v2.u64 {%0,%1}, [%2];"                           \
                     : "=l"(xS[S][2]), "=l"(xS[S][3]) : "r"(xa_ + 16u));         \
    }while(0)

#define CMPSET(S) do{                                                            \
        unsigned long long ww_ = pack2(wS[S], wS[S]);                            \
        acc[0] = ffma2(ww_, xS[S][0], acc[0]);                                   \
        acc[1] = ffma2(ww_, xS[S][1], acc[1]);                                   \
        acc[2] = ffma2(ww_, xS[S][2], acc[2]);                                   \
        acc[3] = ffma2(ww_, xS[S][3], acc[3]);                                   \
    }while(0)

    #pragma unroll 1
    for (int s = 0; s < 8; s++){                 // slice index, kb = s*32
        if (s + 3 < 8){
            float* dst = Wb + ((s + 3) & 3)*4096;
            #pragma unroll
            for (int j = 0; j < 2; j++){
                int id = tid + j*512;
                int kk = id >> 5, c = id & 31;
                cpa16(dst + kk*128 + c*4, wsrc + (size_t)((s+3)*32 + kk)*NROWS + c*4);
            }
            CP_COMMIT;
            CP_WAIT(2);
        } else if (s == 5){ CP_WAIT(2); }
        else if (s == 6){ CP_WAIT(1); }
        else if (s == 7){ CP_WAIT(0); }
        __syncthreads();

        const unsigned woff = wbb + (unsigned)((s & 3)*16384);
        const unsigned xoff = xsb + (unsigned)(s*32)*128u + (unsigned)(bq*32);

        LDSET(0, 0); LDSET(1, 1); LDSET(2, 2);
        #pragma unroll
        for (int kk = 0; kk < 32; kk++){
            if (kk + 3 < 32) LDSET((kk + 3) & 3, kk + 3);
            CMPSET(kk & 3);
        }
        __syncthreads();
    }
#undef LDSET
#undef CMPSET

    float* pp = g_part + ((size_t)split*NROWS + row)*32 + bq*8;
    #pragma unroll
    for (int j = 0; j < 2; j++){
        float2 a = unpack2(acc[2*j]);
        float2 c = unpack2(acc[2*j+1]);
        *(float4*)(pp + j*4) = make_float4(a.x, a.y, c.x, c.y);
    }
}

// ================= gates (FROZEN, R7 bitwise) =================
template<int L>
__global__ void __launch_bounds__(256) lstm_gates(const float* __restrict__ bih,
                                                  const float* __restrict__ bhh)
{
    int idx = blockIdx.x*256 + threadIdx.x;
    int b = idx & 31, u = idx >> 5;
    float g[4];
    #pragma unroll
    for (int gg = 0; gg < 4; gg++){
        int r = gg*HID + u;
        float s = bih[r] + bhh[r];
        #pragma unroll
        for (int sp = 0; sp < KSPLIT; sp++)
            s += g_part[((size_t)sp*NROWS + r)*32 + b];
        g[gg] = s;
    }
    float iv = sigmoidf_(g[0]), fv = sigmoidf_(g[1]), ov = sigmoidf_(g[3]);
    float tv = tanhf(g[2]);
    float* cp = L ? g_c1 : g_c0;
    float* hp = L ? g_h1 : g_h0;
    int id = b*HID + u;
    float cn = fv*cp[id] + iv*tv;
    cp[id] = cn;
    float h = ov*tanhf(cn);
    hp[id] = h;
    if (L == 1) store_hl((unsigned short*)g_XL + b*2048, u, h);
}

// ================= logits: 3-term 2-split bf16 MMA (R9 proven) =================
__global__ void __launch_bounds__(256) logits_mma(const float* __restrict__ blin)
{
    extern __shared__ __align__(16) char sm[];
    const int tid = threadIdx.x, lane = tid & 31, w = tid >> 5;
    const int mi = w & 3, ki = w >> 2;
    const uint4* __restrict__ Wsrc = g_WL + (size_t)blockIdx.x*64*256;
    const uint4* __restrict__ Xsrc = g_XL;

    float d[4][4];
    #pragma unroll
    for (int i = 0; i < 4; i++){ d[i][0]=0.f; d[i][1]=0.f; d[i][2]=0.f; d[i][3]=0.f; }

    {
        char* smw = sm; char* smx = sm + 34816;
        #pragma unroll
        for (int j = 0; j < 8; j++){
            int s = tid + j*256, row = s >> 5, c = s & 31;
            cpa16(smw + row*544 + c*16, Wsrc + (size_t)row*256 + c);
        }
        #pragma unroll
        for (int j = 0; j < 4; j++){
            int s = tid + j*256, row = s >> 5, c = s & 31;
            cpa16(smx + row*544 + c*16, Xsrc + (size_t)row*256 + c);
        }
        CP_COMMIT;
    }

    for (int ck = 0; ck < 8; ck++){
        if (ck < 7){
            char* smw = sm + ((ck+1)&1)*52224; char* smx = smw + 34816;
            #pragma unroll
            for (int j = 0; j < 8; j++){
                int s = tid + j*256, row = s >> 5, c = s & 31;
                cpa16(smw + row*544 + c*16, Wsrc + (size_t)row*256 + (ck+1)*32 + c);
            }
            #pragma unroll
            for (int j = 0; j < 4; j++){
                int s = tid + j*256, row = s >> 5, c = s & 31;
                cpa16(smx + row*544 + c*16, Xsrc + (size_t)row*256 + (ck+1)*32 + c);
            }
            CP_COMMIT;
            CP_WAIT(1);
        } else {
            CP_WAIT(0);
        }
        __syncthreads();
        const char* smw = sm + (ck&1)*52224;
        const char* smx = smw + 34816;
        const int r0 = mi*16 + (lane>>2);
        #pragma unroll
        for (int s = 0; s < 4; s++){
            int ap = (ki*4 + s)*8 + (lane&3);
            uint2 A0 = ld2(smw, r0,   ap);
            uint2 A1 = ld2(smw, r0+8, ap);
            uint2 A2 = ld2(smw, r0,   ap+4);
            uint2 A3 = ld2(smw, r0+8, ap+4);
            #pragma unroll
            for (int nt = 0; nt < 4; nt++){
                int n = nt*8 + (lane>>2);
                uint2 B0 = ld2(smx, n, ap);
                uint2 B1 = ld2(smx, n, ap+4);
                mma16816(d[nt], A0.x,A1.x,A2.x,A3.x, B0.x,B1.x);
                mma16816(d[nt], A0.x,A1.x,A2.x,A3.x, B0.y,B1.y);
                mma16816(d[nt], A0.y,A1.y,A2.y,A3.y, B0.x,B1.x);
            }
        }
        __syncthreads();
    }

    float* Gs = (float*)sm;
    {
        int r = mi*16 + (lane>>2), cb = (lane&3)*2;
        #pragma unroll
        for (int nt = 0; nt < 4; nt++){
            int n = nt*8 + cb;
            Gs[(ki*64 + r  )*33 + n  ] = d[nt][0];
            Gs[(ki*64 + r  )*33 + n+1] = d[nt][1];
            Gs[(ki*64 + r+8)*33 + n  ] = d[nt][2];
            Gs[(ki*64 + r+8)*33 + n+1] = d[nt][3];
        }
    }
    __syncthreads();
    #pragma unroll
    for (int j = 0; j < 8; j++){
        int idx = tid + j*256;
        int b = idx >> 6, r = idx & 63;
        int v = blockIdx.x*64 + r;
        g_logits[(size_t)b*V + v] = Gs[r*33 + b] + Gs[(64 + r)*33 + b] + blin[v];
    }
}

// ================= fused: online softmax + per-chunk exact argmax candidates =================
#define CHUNK (V/8)   // 4000

__global__ void __launch_bounds__(256) smax12c(const float* __restrict__ Wlin,
                                               const float* __restrict__ blin){
    __shared__ float sm[256], ss[256];
    __shared__ int   cand[32];
    __shared__ float cval[32];
    __shared__ int   ncand;
    int c = blockIdx.x, b = blockIdx.y, tid = threadIdx.x;
    if (tid == 0) ncand = 0;
    const float* row = g_logits + (size_t)b*V + c*CHUNK;

    float m = -INFINITY, s = 0.f;
    for (int v = tid; v < CHUNK; v += 256){
        float x = row[v];
        if (x > m){ s *= expf(m - x); m = x; }
        s += expf(x - m);
    }
    sm[tid] = m; ss[tid] = s;
    __syncthreads();
    for (int st = 128; st > 0; st >>= 1){
        if (tid < st){
            float m2 = sm[tid+st], s2 = ss[tid+st];
            float M = fmaxf(sm[tid], m2);
            ss[tid] = ss[tid]*expf(sm[tid]-M) + s2*expf(m2-M);
            sm[tid] = M;
        }
        __syncthreads();
    }
    const float lmax = sm[0];
    if (tid == 0){ g_pm[b*8+c] = lmax; g_ps[b*8+c] = ss[0]; }

    const float thr = lmax - 1e-3f;
    for (int v = tid; v < CHUNK; v += 256){
        if (row[v] >= thr){
            int sl = atomicAdd(&ncand, 1);
            if (sl < 32) cand[sl] = v + c*CHUNK;
        }
    }
    __syncthreads();
    int nc = min(ncand, 32);
    int w = tid >> 5, lane = tid & 31;
    const float* h = g_h1 + b*HID;
    for (int ci = w; ci < nc; ci += 8){
        int v = cand[ci];
        const float* wr = Wlin + (size_t)v*1024;
        float acc = 0.f;
        #pragma unroll 8
        for (int k = lane; k < 1024; k += 32) acc += h[k]*wr[k];
        #pragma unroll
        for (int o = 16; o > 0; o >>= 1) acc += __shfl_xor_sync(0xffffffffu, acc, o);
        if (lane == 0) cval[ci] = acc + blin[v];
    }
    __syncthreads();
    if (tid == 0){
        float bm = -INFINITY; int bi = 1<<30;
        for (int i = 0; i < nc; i++){
            if (cval[i] > bm || (cval[i] == bm && cand[i] < bi)){ bm = cval[i]; bi = cand[i]; }
        }
        g_cv[b*8+c] = bm; g_ci[b*8+c] = bi;
    }
}

// ================= normalize + write probs (streaming stores) + combine argmax =================
__global__ void __launch_bounds__(256) smax3(float* __restrict__ out, int t){
    int c = blockIdx.x, b = blockIdx.y, tid = threadIdx.x;
    if (c == 0 && tid == 0){
        float bm = -INFINITY; int bi = 1<<30;
        #pragma unroll
        for (int i = 0; i < 8; i++){
            float v = g_cv[b*8+i]; int ix = g_ci[b*8+i];
            if (v > bm || (v == bm && ix < bi)){ bm = v; bi = ix; }
        }
        g_tok[b] = bi;
    }
    float gm = g_pm[b*8];
    #pragma unroll
    for (int i = 1; i < 8; i++) gm = fmaxf(gm, g_pm[b*8+i]);
    float sum = 0.f;
    #pragma unroll
    for (int i = 0; i < 8; i++) sum += g_ps[b*8+i]*expf(g_pm[b*8+i] - gm);
    float inv = 1.0f / sum;
    const float* row = g_logits + (size_t)b*V + c*CHUNK;
    float* dst = out + ((size_t)b*TSTEPS + t)*V + c*CHUNK;
    for (int v = tid; v < CHUNK; v += 256)
        __stcs(dst + v, expf(row[v] - gm) * inv);
}

// ================= launch =================
extern "C" void kernel_launch(void* const* d_in, const int* in_sizes, int n_in,
                              void* d_out, int out_size)
{
    int s = (n_in >= 13) ? 1 : ((in_sizes[1] == 1) ? 1 : 0);
    const float* ctx  = (const float*)d_in[0];
    const float* emb  = (const float*)d_in[1+s];
    const float* Wih0 = (const float*)d_in[2+s];
    const float* Whh0 = (const float*)d_in[3+s];
    const float* bih0 = (const float*)d_in[4+s];
    const float* bhh0 = (const float*)d_in[5+s];
    const float* Wih1 = (const float*)d_in[6+s];
    const float* Whh1 = (const float*)d_in[7+s];
    const float* bih1 = (const float*)d_in[8+s];
    const float* bhh1 = (const float*)d_in[9+s];
    const float* Wlin = (const float*)d_in[10+s];
    const float* blin = (const float*)d_in[11+s];
    float* out = (float*)d_out;

    const int LGSM = (8192 + 16384)*4;   // 98304 B: Xs 32KB + Wb 64KB
    cudaFuncSetAttribute(lstm_gemm<0>, cudaFuncAttributeMaxDynamicSharedMemorySize, LGSM);
    cudaFuncSetAttribute(lstm_gemm<1>, cudaFuncAttributeMaxDynamicSharedMemorySize, LGSM);
    cudaFuncSetAttribute(logits_mma, cudaFuncAttributeMaxDynamicSharedMemorySize, 104448);

    init_kernel<<<128, 256>>>();
    tr_lstm<0><<<dim3(NROWS/32, K2/32), dim3(32,8)>>>(Wih0, Whh0);
    tr_lstm<1><<<dim3(NROWS/32, K2/32), dim3(32,8)>>>(Wih1, Whh1);

    for (int t = 0; t < TSTEPS; t++){
        lstm_gemm<0><<<256, 512, LGSM>>>(emb, ctx);
        lstm_gates<0><<<128, 256>>>(bih0, bhh0);
        lstm_gemm<1><<<256, 512, LGSM>>>(emb, ctx);
        lstm_gates<1><<<128, 256>>>(bih1, bhh1);
        if (t == 0) prep_lin<<<V, 256>>>(Wlin);
        logits_mma<<<500, 256, 104448>>>(blin);
        smax12c<<<dim3(8,B), 256>>>(Wlin, blin);
        smax3<<<dim3(8,B), 256>>>(out, t);
    }
}

// round 17
// speedup vs baseline: 1.1815x; 1.1815x over previous
#include <cuda_runtime.h>
#include <cuda_bf16.h>
#include <math.h>

#define B       32
#define HID     1024
#define K2      2048
#define V       32000
#define TSTEPS  64
#define NROWS   4096
#define KSPLIT  8
#define KCHUNK  256
#define START_TOK 1

// ================= persistent device scratch =================
__device__ float g_Wt0[(size_t)K2*NROWS];   // layer0 [Wih|Whh]^T [k][row]  (fp32)
__device__ float g_Wt1[(size_t)K2*NROWS];
__device__ uint4 g_WL[(size_t)V*256];       // W_lin 2-split bf16 interleaved
__device__ uint4 g_XL[32*256];              // h1 2-split bf16
__device__ float g_h0[B*HID], g_c0[B*HID], g_h1[B*HID], g_c1[B*HID];
__device__ float g_part[(size_t)KSPLIT*NROWS*B];
__device__ float g_logits[(size_t)B*V];
__device__ int   g_tok[B];
__device__ float g_pm[B*8], g_ps[B*8];
__device__ float g_cv[B*8];
__device__ int   g_ci[B*8];

// ================= f32x2 helpers (accumulation chains FROZEN, R7 bitwise) =================
static __device__ __forceinline__ unsigned long long ffma2(unsigned long long a,
                                                           unsigned long long b,
                                                           unsigned long long c){
    unsigned long long d;
    asm("fma.rn.f32x2 %0, %1, %2, %3;" : "=l"(d) : "l"(a), "l"(b), "l"(c));
    return d;
}
static __device__ __forceinline__ unsigned long long pack2(float x, float y){
    unsigned long long d;
    asm("mov.b64 %0, {%1, %2};" : "=l"(d) : "f"(x), "f"(y));
    return d;
}
static __device__ __forceinline__ float2 unpack2(unsigned long long a){
    float2 r;
    asm("mov.b64 {%0, %1}, %2;" : "=f"(r.x), "=f"(r.y) : "l"(a));
    return r;
}
static __device__ __forceinline__ float sigmoidf_(float x){ return 1.0f/(1.0f + expf(-x)); }

// ================= bf16 helpers (logits path) =================
static __device__ __forceinline__ unsigned short f2bf(float x){
    __nv_bfloat16 h = __float2bfloat16(x);
    return *reinterpret_cast<unsigned short*>(&h);
}
static __device__ __forceinline__ float bf2f(unsigned short u){
    __nv_bfloat16 h = *reinterpret_cast<__nv_bfloat16*>(&u);
    return __bfloat162float(h);
}
static __device__ __forceinline__ uint4 pack4(float4 v){
    unsigned short hx=f2bf(v.x), hy=f2bf(v.y), hz=f2bf(v.z), hw=f2bf(v.w);
    unsigned short lx=f2bf(v.x-bf2f(hx)), ly=f2bf(v.y-bf2f(hy));
    unsigned short lz=f2bf(v.z-bf2f(hz)), lw=f2bf(v.w-bf2f(hw));
    uint4 o;
    o.x = (unsigned)hx | ((unsigned)hy<<16);
    o.y = (unsigned)lx | ((unsigned)ly<<16);
    o.z = (unsigned)hz | ((unsigned)hw<<16);
    o.w = (unsigned)lz | ((unsigned)lw<<16);
    return o;
}
static __device__ __forceinline__ void store_hl(unsigned short* rowbase, int k, float v){
    unsigned short hi = f2bf(v);
    unsigned short lo = f2bf(v - bf2f(hi));
    int idx = (k>>2)*8 + ((k>>1)&1)*4 + (k&1);
    rowbase[idx]   = hi;
    rowbase[idx+2] = lo;
}
static __device__ __forceinline__ void cpa16(void* dst, const void* src){
    unsigned ds = (unsigned)__cvta_generic_to_shared(dst);
    asm volatile("cp.async.cg.shared.global [%0], [%1], 16;\n" :: "r"(ds), "l"(src));
}
#define CP_COMMIT asm volatile("cp.async.commit_group;\n")
#define CP_WAIT(n) asm volatile("cp.async.wait_group %0;\n" :: "n"(n))
static __device__ __forceinline__ uint2 ld2(const char* base, int row, int pair){
    return *(const uint2*)(base + row*544 + pair*8);
}
static __device__ __forceinline__ void mma16816(float* d,
    unsigned a0, unsigned a1, unsigned a2, unsigned a3, unsigned b0, unsigned b1){
    asm volatile("mma.sync.aligned.m16n8k16.row.col.f32.bf16.bf16.f32 "
        "{%0,%1,%2,%3},{%4,%5,%6,%7},{%8,%9},{%0,%1,%2,%3};"
        : "+f"(d[0]), "+f"(d[1]), "+f"(d[2]), "+f"(d[3])
        : "r"(a0), "r"(a1), "r"(a2), "r"(a3), "r"(b0), "r"(b1));
}

// ================= init =================
__global__ void init_kernel(){
    int i = blockIdx.x*blockDim.x + threadIdx.x;
    if (i < B*HID){ g_h0[i]=0.f; g_c0[i]=0.f; g_h1[i]=0.f; g_c1[i]=0.f; }
    if (i < 8192) ((uint4*)g_XL)[i] = make_uint4(0,0,0,0);
    if (i < B) g_tok[i] = START_TOK;
}

// ================= prep =================
template<int L>
__global__ void tr_lstm(const float* __restrict__ Wih, const float* __restrict__ Whh){
    __shared__ float t[32][33];
    int rb = blockIdx.x*32, kb = blockIdx.y*32;
    int x = threadIdx.x, y = threadIdx.y;
    const float* src = (kb < 1024) ? Wih : Whh;
    int ko = (kb < 1024) ? kb : kb - 1024;
    #pragma unroll
    for (int j = 0; j < 32; j += 8) t[y+j][x] = src[(size_t)(rb+y+j)*1024 + ko + x];
    __syncthreads();
    float* dst = L ? g_Wt1 : g_Wt0;
    #pragma unroll
    for (int j = 0; j < 32; j += 8) dst[(size_t)(kb+y+j)*NROWS + rb + x] = t[x][y+j];
}
__global__ void prep_lin(const float* __restrict__ W){
    int v = blockIdx.x, j = threadIdx.x;
    float4 x = *(const float4*)(W + (size_t)v*1024 + j*4);
    g_WL[(size_t)v*256 + j] = pack4(x);
}

// ================= LSTM GEMM partials — retile: thread = 2 rows x 8 batches =================
// 256 blocks x 256 thr. lrow = tid&63 -> rows (2*lrow, 2*lrow+1); bg = tid>>6 -> batches bg*8..+7.
// Per-(row,batch-pair) FFMA2 chains bitwise identical to R7: k strictly ascending within
// split, same operand pairs (2m,2m+1), same output bytes. W via R14 4-deep cp.async pipeline.
template<int L>
__global__ void __launch_bounds__(256) lstm_gemm(const float* __restrict__ emb,
                                                 const float* __restrict__ ctx)
{
    extern __shared__ __align__(16) float smf[];
    float* Xs = smf;                 // [256][32] = 8192 floats (32KB)
    float* Wb = smf + 8192;          // [4][32][128] = 16384 floats (64KB)
    const int tid   = threadIdx.x;
    const int split = blockIdx.x & 7;
    const int rb    = (blockIdx.x >> 3)*128;
    const int lrow  = tid & 63;           // row pair index
    const int bg    = tid >> 6;           // 0..3
    const int kbase = split*KCHUNK;
    const float* __restrict__ Wt = L ? g_Wt1 : g_Wt0;
    const float* __restrict__ wsrc = Wt + (size_t)kbase*NROWS + rb;

    // ---- stage X chunk (same contents as R7/R14) ----
    {
        int b = tid >> 3, q = tid & 7;
        const float* src;
        if (L == 0){
            if (split < 2)      src = emb + (size_t)g_tok[b]*512 + kbase;
            else if (split < 4) src = ctx + (size_t)b*512 + (kbase - 512);
            else                src = g_h0 + b*HID + (kbase - 1024);
        } else {
            if (split < 4)      src = g_h0 + b*HID + kbase;
            else                src = g_h1 + b*HID + (kbase - 1024);
        }
        #pragma unroll
        for (int i = 0; i < 8; i++){
            int kf = (q + i*8)*4;
            float4 v = *(const float4*)(src + kf);
            Xs[(kf+0)*32+b]=v.x; Xs[(kf+1)*32+b]=v.y;
            Xs[(kf+2)*32+b]=v.z; Xs[(kf+3)*32+b]=v.w;
        }
    }

    // ---- prefetch W slices 0..2 (3 groups in flight) ----
    #pragma unroll
    for (int p = 0; p < 3; p++){
        float* dst = Wb + p*4096;
        #pragma unroll
        for (int j = 0; j < 4; j++){
            int id = tid + j*256;
            int kk = id >> 5, c = id & 31;
            cpa16(dst + kk*128 + c*4, wsrc + (size_t)(p*32 + kk)*NROWS + c*4);
        }
        CP_COMMIT;
    }

    unsigned long long accA[4] = {0ull,0ull,0ull,0ull};   // row 2*lrow
    unsigned long long accB[4] = {0ull,0ull,0ull,0ull};   // row 2*lrow+1

    #pragma unroll
    for (int s = 0; s < 8; s++){                 // slice index, kb = s*32
        if (s + 3 < 8){
            float* dst = Wb + ((s + 3) & 3)*4096;
            #pragma unroll
            for (int j = 0; j < 4; j++){
                int id = tid + j*256;
                int kk = id >> 5, c = id & 31;
                cpa16(dst + kk*128 + c*4, wsrc + (size_t)((s+3)*32 + kk)*NROWS + c*4);
            }
            CP_COMMIT;
        }
        if (s < 6)      { CP_WAIT(2); }
        else if (s == 6){ CP_WAIT(1); }
        else            { CP_WAIT(0); }
        __syncthreads();

        const float* wcur = Wb + (s & 3)*4096;
        const int kb = s*32;
        #pragma unroll
        for (int kk = 0; kk < 32; kk++){
            float2 w2 = *(const float2*)&wcur[kk*128 + 2*lrow];
            unsigned long long w0 = pack2(w2.x, w2.x);
            unsigned long long w1 = pack2(w2.y, w2.y);
            const ulonglong2* xr = (const ulonglong2*)(Xs + (kb + kk)*32 + bg*8);
            ulonglong2 xa = xr[0];
            ulonglong2 xb = xr[1];
            accA[0] = ffma2(w0, xa.x, accA[0]);
            accA[1] = ffma2(w0, xa.y, accA[1]);
            accA[2] = ffma2(w0, xb.x, accA[2]);
            accA[3] = ffma2(w0, xb.y, accA[3]);
            accB[0] = ffma2(w1, xa.x, accB[0]);
            accB[1] = ffma2(w1, xa.y, accB[1]);
            accB[2] = ffma2(w1, xb.x, accB[2]);
            accB[3] = ffma2(w1, xb.y, accB[3]);
        }
        __syncthreads();
    }

    // ---- store partials (identical bytes/addresses to R7 layout) ----
    {
        int row0 = rb + 2*lrow;
        float* pp0 = g_part + ((size_t)split*NROWS + row0)*32 + bg*8;
        float* pp1 = pp0 + 32;
        float2 a0 = unpack2(accA[0]), a1 = unpack2(accA[1]);
        float2 a2 = unpack2(accA[2]), a3 = unpack2(accA[3]);
        *(float4*)(pp0    ) = make_float4(a0.x, a0.y, a1.x, a1.y);
        *(float4*)(pp0 + 4) = make_float4(a2.x, a2.y, a3.x, a3.y);
        float2 b0 = unpack2(accB[0]), b1 = unpack2(accB[1]);
        float2 b2 = unpack2(accB[2]), b3 = unpack2(accB[3]);
        *(float4*)(pp1    ) = make_float4(b0.x, b0.y, b1.x, b1.y);
        *(float4*)(pp1 + 4) = make_float4(b2.x, b2.y, b3.x, b3.y);
    }
}

// ================= gates (FROZEN, R7 bitwise) =================
template<int L>
__global__ void __launch_bounds__(256) lstm_gates(const float* __restrict__ bih,
                                                  const float* __restrict__ bhh)
{
    int idx = blockIdx.x*256 + threadIdx.x;
    int b = idx & 31, u = idx >> 5;
    float g[4];
    #pragma unroll
    for (int gg = 0; gg < 4; gg++){
        int r = gg*HID + u;
        float s = bih[r] + bhh[r];
        #pragma unroll
        for (int sp = 0; sp < KSPLIT; sp++)
            s += g_part[((size_t)sp*NROWS + r)*32 + b];
        g[gg] = s;
    }
    float iv = sigmoidf_(g[0]), fv = sigmoidf_(g[1]), ov = sigmoidf_(g[3]);
    float tv = tanhf(g[2]);
    float* cp = L ? g_c1 : g_c0;
    float* hp = L ? g_h1 : g_h0;
    int id = b*HID + u;
    float cn = fv*cp[id] + iv*tv;
    cp[id] = cn;
    float h = ov*tanhf(cn);
    hp[id] = h;
    if (L == 1) store_hl((unsigned short*)g_XL + b*2048, u, h);
}

// ================= logits: 3-term 2-split bf16 MMA (R9 proven) =================
__global__ void __launch_bounds__(256) logits_mma(const float* __restrict__ blin)
{
    extern __shared__ __align__(16) char sm[];
    const int tid = threadIdx.x, lane = tid & 31, w = tid >> 5;
    const int mi = w & 3, ki = w >> 2;
    const uint4* __restrict__ Wsrc = g_WL + (size_t)blockIdx.x*64*256;
    const uint4* __restrict__ Xsrc = g_XL;

    float d[4][4];
    #pragma unroll
    for (int i = 0; i < 4; i++){ d[i][0]=0.f; d[i][1]=0.f; d[i][2]=0.f; d[i][3]=0.f; }

    {
        char* smw = sm; char* smx = sm + 34816;
        #pragma unroll
        for (int j = 0; j < 8; j++){
            int s = tid + j*256, row = s >> 5, c = s & 31;
            cpa16(smw + row*544 + c*16, Wsrc + (size_t)row*256 + c);
        }
        #pragma unroll
        for (int j = 0; j < 4; j++){
            int s = tid + j*256, row = s >> 5, c = s & 31;
            cpa16(smx + row*544 + c*16, Xsrc + (size_t)row*256 + c);
        }
        CP_COMMIT;
    }

    for (int ck = 0; ck < 8; ck++){
        if (ck < 7){
            char* smw = sm + ((ck+1)&1)*52224; char* smx = smw + 34816;
            #pragma unroll
            for (int j = 0; j < 8; j++){
                int s = tid + j*256, row = s >> 5, c = s & 31;
                cpa16(smw + row*544 + c*16, Wsrc + (size_t)row*256 + (ck+1)*32 + c);
            }
            #pragma unroll
            for (int j = 0; j < 4; j++){
                int s = tid + j*256, row = s >> 5, c = s & 31;
                cpa16(smx + row*544 + c*16, Xsrc + (size_t)row*256 + (ck+1)*32 + c);
            }
            CP_COMMIT;
            CP_WAIT(1);
        } else {
            CP_WAIT(0);
        }
        __syncthreads();
        const char* smw = sm + (ck&1)*52224;
        const char* smx = smw + 34816;
        const int r0 = mi*16 + (lane>>2);
        #pragma unroll
        for (int s = 0; s < 4; s++){
            int ap = (ki*4 + s)*8 + (lane&3);
            uint2 A0 = ld2(smw, r0,   ap);
            uint2 A1 = ld2(smw, r0+8, ap);
            uint2 A2 = ld2(smw, r0,   ap+4);
            uint2 A3 = ld2(smw, r0+8, ap+4);
            #pragma unroll
            for (int nt = 0; nt < 4; nt++){
                int n = nt*8 + (lane>>2);
                uint2 B0 = ld2(smx, n, ap);
                uint2 B1 = ld2(smx, n, ap+4);
                mma16816(d[nt], A0.x,A1.x,A2.x,A3.x, B0.x,B1.x);
                mma16816(d[nt], A0.x,A1.x,A2.x,A3.x, B0.y,B1.y);
                mma16816(d[nt], A0.y,A1.y,A2.y,A3.y, B0.x,B1.x);
            }
        }
        __syncthreads();
    }

    float* Gs = (float*)sm;
    {
        int r = mi*16 + (lane>>2), cb = (lane&3)*2;
        #pragma unroll
        for (int nt = 0; nt < 4; nt++){
            int n = nt*8 + cb;
            Gs[(ki*64 + r  )*33 + n  ] = d[nt][0];
            Gs[(ki*64 + r  )*33 + n+1] = d[nt][1];
            Gs[(ki*64 + r+8)*33 + n  ] = d[nt][2];
            Gs[(ki*64 + r+8)*33 + n+1] = d[nt][3];
        }
    }
    __syncthreads();
    #pragma unroll
    for (int j = 0; j < 8; j++){
        int idx = tid + j*256;
        int b = idx >> 6, r = idx & 63;
        int v = blockIdx.x*64 + r;
        g_logits[(size_t)b*V + v] = Gs[r*33 + b] + Gs[(64 + r)*33 + b] + blin[v];
    }
}

// ================= fused: online softmax + per-chunk exact argmax candidates =================
#define CHUNK (V/8)   // 4000

__global__ void __launch_bounds__(256) smax12c(const float* __restrict__ Wlin,
                                               const float* __restrict__ blin){
    __shared__ float sm[256], ss[256];
    __shared__ int   cand[32];
    __shared__ float cval[32];
    __shared__ int   ncand;
    int c = blockIdx.x, b = blockIdx.y, tid = threadIdx.x;
    if (tid == 0) ncand = 0;
    const float* row = g_logits + (size_t)b*V + c*CHUNK;

    float m = -INFINITY, s = 0.f;
    for (int v = tid; v < CHUNK; v += 256){
        float x = row[v];
        if (x > m){ s *= expf(m - x); m = x; }
        s += expf(x - m);
    }
    sm[tid] = m; ss[tid] = s;
    __syncthreads();
    for (int st = 128; st > 0; st >>= 1){
        if (tid < st){
            float m2 = sm[tid+st], s2 = ss[tid+st];
            float M = fmaxf(sm[tid], m2);
            ss[tid] = ss[tid]*expf(sm[tid]-M) + s2*expf(m2-M);
            sm[tid] = M;
        }
        __syncthreads();
    }
    const float lmax = sm[0];
    if (tid == 0){ g_pm[b*8+c] = lmax; g_ps[b*8+c] = ss[0]; }

    const float thr = lmax - 1e-3f;
    for (int v = tid; v < CHUNK; v += 256){
        if (row[v] >= thr){
            int sl = atomicAdd(&ncand, 1);
            if (sl < 32) cand[sl] = v + c*CHUNK;
        }
    }
    __syncthreads();
    int nc = min(ncand, 32);
    int w = tid >> 5, lane = tid & 31;
    const float* h = g_h1 + b*HID;
    for (int ci = w; ci < nc; ci += 8){
        int v = cand[ci];
        const float* wr = Wlin + (size_t)v*1024;
        float acc = 0.f;
        #pragma unroll 8
        for (int k = lane; k < 1024; k += 32) acc += h[k]*wr[k];
        #pragma unroll
        for (int o = 16; o > 0; o >>= 1) acc += __shfl_xor_sync(0xffffffffu, acc, o);
        if (lane == 0) cval[ci] = acc + blin[v];
    }
    __syncthreads();
    if (tid == 0){
        float bm = -INFINITY; int bi = 1<<30;
        for (int i = 0; i < nc; i++){
            if (cval[i] > bm || (cval[i] == bm && cand[i] < bi)){ bm = cval[i]; bi = cand[i]; }
        }
        g_cv[b*8+c] = bm; g_ci[b*8+c] = bi;
    }
}

// ================= normalize + write probs (streaming stores) + combine argmax =================
__global__ void __launch_bounds__(256) smax3(float* __restrict__ out, int t){
    int c = blockIdx.x, b = blockIdx.y, tid = threadIdx.x;
    if (c == 0 && tid == 0){
        float bm = -INFINITY; int bi = 1<<30;
        #pragma unroll
        for (int i = 0; i < 8; i++){
            float v = g_cv[b*8+i]; int ix = g_ci[b*8+i];
            if (v > bm || (v == bm && ix < bi)){ bm = v; bi = ix; }
        }
        g_tok[b] = bi;
    }
    float gm = g_pm[b*8];
    #pragma unroll
    for (int i = 1; i < 8; i++) gm = fmaxf(gm, g_pm[b*8+i]);
    float sum = 0.f;
    #pragma unroll
    for (int i = 0; i < 8; i++) sum += g_ps[b*8+i]*expf(g_pm[b*8+i] - gm);
    float inv = 1.0f / sum;
    const float* row = g_logits + (size_t)b*V + c*CHUNK;
    float* dst = out + ((size_t)b*TSTEPS + t)*V + c*CHUNK;
    for (int v = tid; v < CHUNK; v += 256)
        __stcs(dst + v, expf(row[v] - gm) * inv);
}

// ================= launch =================
extern "C" void kernel_launch(void* const* d_in, const int* in_sizes, int n_in,
                              void* d_out, int out_size)
{
    int s = (n_in >= 13) ? 1 : ((in_sizes[1] == 1) ? 1 : 0);
    const float* ctx  = (const float*)d_in[0];
    const float* emb  = (const float*)d_in[1+s];
    const float* Wih0 = (const float*)d_in[2+s];
    const float* Whh0 = (const float*)d_in[3+s];
    const float* bih0 = (const float*)d_in[4+s];
    const float* bhh0 = (const float*)d_in[5+s];
    const float* Wih1 = (const float*)d_in[6+s];
    const float* Whh1 = (const float*)d_in[7+s];
    const float* bih1 = (const float*)d_in[8+s];
    const float* bhh1 = (const float*)d_in[9+s];
    const float* Wlin = (const float*)d_in[10+s];
    const float* blin = (const float*)d_in[11+s];
    float* out = (float*)d_out;

    const int LGSM = (8192 + 16384)*4;   // 98304 B: Xs 32KB + Wb 64KB
    cudaFuncSetAttribute(lstm_gemm<0>, cudaFuncAttributeMaxDynamicSharedMemorySize, LGSM);
    cudaFuncSetAttribute(lstm_gemm<1>, cudaFuncAttributeMaxDynamicSharedMemorySize, LGSM);
    cudaFuncSetAttribute(logits_mma, cudaFuncAttributeMaxDynamicSharedMemorySize, 104448);

    init_kernel<<<128, 256>>>();
    tr_lstm<0><<<dim3(NROWS/32, K2/32), dim3(32,8)>>>(Wih0, Whh0);
    tr_lstm<1><<<dim3(NROWS/32, K2/32), dim3(32,8)>>>(Wih1, Whh1);

    for (int t = 0; t < TSTEPS; t++){
        lstm_gemm<0><<<256, 256, LGSM>>>(emb, ctx);
        lstm_gates<0><<<128, 256>>>(bih0, bhh0);
        lstm_gemm<1><<<256, 256, LGSM>>>(emb, ctx);
        lstm_gates<1><<<128, 256>>>(bih1, bhh1);
        if (t == 0) prep_lin<<<V, 256>>>(Wlin);
        logits_mma<<<500, 256, 104448>>>(blin);
        smax12c<<<dim3(8,B), 256>>>(Wlin, blin);
        smax3<<<dim3(8,B), 256>>>(out, t);
    }
}